// round 16
// baseline (speedup 1.0000x reference)
#include <cuda_runtime.h>
#include <cuda_fp16.h>
#include <cstdint>

// ============================================================
// y[m,n] = (sum_k x[m,k]*sign[n,k]) * scale[n] + bias[n]
// M=8192, N=4096, K=4096, fp32 in/out.
// sm_103 base target (no tcgen05) -> mma.sync.m16n8k16 fp16.
// R16: R15 GEMM verbatim + conversion FUSED into the GEMM via
// deadlock-free work-stealing (ticket/count per k-block), so the
// 41us fp32->fp16 pass hides in the GEMM's idle memory pipe.
// ============================================================

static constexpr int MM = 8192;
static constexpr int NN = 4096;
static constexpr int KK = 4096;

static constexpr int BM = 128;
static constexpr int BN = 128;
static constexpr int BK = 64;               // 64 fp16 = 128B rows
static constexpr int STAGES = 3;
static constexpr int KT = KK / BK;          // 64 k-blocks

static constexpr int A_STAGE_BYTES = BM * BK * 2;   // 16384
static constexpr int B_STAGE_BYTES = BN * BK * 2;   // 16384
static constexpr int STAGE_BYTES = A_STAGE_BYTES + B_STAGE_BYTES; // 32768
static constexpr int SMEM_TOTAL = STAGES * STAGE_BYTES;           // 98304

// conversion work decomposition: per k-block (64 cols), rows of x (8192)
// + rows of w (4096) = 12288 rows -> 48 chunks of 256 rows.
static constexpr int CHUNK_ROWS = 256;
static constexpr int S_CHUNKS = (MM + NN) / CHUNK_ROWS;   // 48

// fp16 scratch + conversion progress (device globals)
__device__ __half g_xh[(size_t)MM * KK];    // 64 MB
__device__ __half g_wh[(size_t)NN * KK];    // 32 MB
__device__ int g_ticket[KT];
__device__ int g_cnt[KT];

// ---------------- PTX helpers ----------------
__device__ __forceinline__ uint32_t smem_u32(const void* p) {
    uint32_t a;
    asm("{ .reg .u64 t; cvta.to.shared.u64 t, %1; cvt.u32.u64 %0, t; }"
        : "=r"(a) : "l"(p));
    return a;
}

#define CP_ASYNC16(smem, gmem) \
    asm volatile("cp.async.cg.shared.global [%0], [%1], 16;" \
                 :: "r"(smem), "l"(gmem) : "memory")
#define CP_COMMIT() asm volatile("cp.async.commit_group;" ::: "memory")
#define CP_WAIT(n)  asm volatile("cp.async.wait_group %0;" :: "n"(n) : "memory")

__device__ __forceinline__ void ldsm4(uint32_t* r, uint32_t addr) {
    asm volatile("ldmatrix.sync.aligned.m8n8.x4.shared.b16 {%0,%1,%2,%3}, [%4];"
                 : "=r"(r[0]), "=r"(r[1]), "=r"(r[2]), "=r"(r[3]) : "r"(addr));
}

__device__ __forceinline__ void mma16816(float* d, const uint32_t* a,
                                         const uint32_t* b) {
    asm volatile(
        "mma.sync.aligned.m16n8k16.row.col.f32.f16.f16.f32 "
        "{%0,%1,%2,%3}, {%4,%5,%6,%7}, {%8,%9}, {%0,%1,%2,%3};"
        : "+f"(d[0]), "+f"(d[1]), "+f"(d[2]), "+f"(d[3])
        : "r"(a[0]), "r"(a[1]), "r"(a[2]), "r"(a[3]), "r"(b[0]), "r"(b[1]));
}

// XOR swizzle: 128B rows of 8 x 16B chunks, chunk ^= (row & 7)
__device__ __forceinline__ uint32_t sw_off(int row, int chunk) {
    return (uint32_t)(row * 128 + ((chunk ^ (row & 7)) << 4));
}

// convert one chunk (kb, c): 256 rows x 64 cols fp32 -> fp16, one row/thread
__device__ __forceinline__ void convert_chunk(const float* __restrict__ x,
                                              const float* __restrict__ w,
                                              int kb, int c, int tid) {
    const int r = c * CHUNK_ROWS + tid;
    const float* src;
    __half* dst;
    if (r < MM) {
        src = x + (size_t)r * KK + kb * BK;
        dst = g_xh + (size_t)r * KK + kb * BK;
    } else {
        const int rw = r - MM;
        src = w + (size_t)rw * KK + kb * BK;
        dst = g_wh + (size_t)rw * KK + kb * BK;
    }
    #pragma unroll
    for (int j = 0; j < 8; j++) {
        const float4 v0 = *reinterpret_cast<const float4*>(src + j * 8);
        const float4 v1 = *reinterpret_cast<const float4*>(src + j * 8 + 4);
        const __half2 a = __floats2half2_rn(v0.x, v0.y);
        const __half2 b = __floats2half2_rn(v0.z, v0.w);
        const __half2 cc = __floats2half2_rn(v1.x, v1.y);
        const __half2 d = __floats2half2_rn(v1.z, v1.w);
        uint4 u;
        u.x = *reinterpret_cast<const unsigned*>(&a);
        u.y = *reinterpret_cast<const unsigned*>(&b);
        u.z = *reinterpret_cast<const unsigned*>(&cc);
        u.w = *reinterpret_cast<const unsigned*>(&d);
        *reinterpret_cast<uint4*>(dst + j * 8) = u;
    }
}

// ---------------- kernels ----------------

__global__ void init_kernel() {
    const int i = threadIdx.x;
    if (i < KT) { g_ticket[i] = 0; g_cnt[i] = 0; }
}

__global__ void __launch_bounds__(256, 2) gemm_kernel(
    float* __restrict__ out,
    const float* __restrict__ scale,
    const float* __restrict__ bias,
    const float* __restrict__ xp,
    const float* __restrict__ wp)
{
    extern __shared__ char smem[];
    __shared__ int s_task[3];   // [0]=kb, [1]=chunk, [2]=ready-flag
    const uint32_t sb = smem_u32(smem);
    const int tid = threadIdx.x;
    const int wid = tid >> 5;
    const int lane = tid & 31;
    const int warp_m = wid & 1;    // 2 warps over M (64 rows each)
    const int warp_n = wid >> 1;   // 4 warps over N (32 cols each)

    // conversion bookkeeping (tid0's copies are authoritative)
    int scan_kb = 0;      // next kb to steal chunks from
    int pend_kb = -1;     // converted last iter, publish this iter
    int last_ready = -1;  // highest kb verified fully converted

    // tid0: grab one unconverted chunk, if any remain
    auto grab_one = [&](int& kbf, int& cf) {
        kbf = -1; cf = -1;
        while (scan_kb < KT) {
            const int c = atomicAdd(&g_ticket[scan_kb], 1);
            if (c < S_CHUNKS) { kbf = scan_kb; cf = c; break; }
            scan_kb++;
        }
    };
    // tid0: advance verified-ready prefix
    auto advance_ready = [&]() {
        while (last_ready + 1 < KT &&
               atomicAdd(&g_cnt[last_ready + 1], 0) >= S_CHUNKS)
            last_ready++;
    };
    // all threads: block until k-block `target` fully converted, helping.
    // Blocked CTAs publish immediately inside the loop, so they never hold
    // unpublished chunks -> no circular wait; resident CTAs can complete
    // all conversion themselves -> deadlock-free.
    auto help_until = [&](int target) {
        #pragma unroll 1
        for (;;) {
            __syncthreads();
            if (tid == 0) {
                advance_ready();
                if (last_ready >= target) {
                    __threadfence();
                    s_task[0] = -1; s_task[2] = 1;
                } else {
                    int kbf, cf;
                    grab_one(kbf, cf);
                    s_task[0] = kbf; s_task[1] = cf; s_task[2] = 0;
                }
            }
            __syncthreads();
            if (s_task[2]) break;
            if (s_task[0] >= 0) {
                convert_chunk(xp, wp, s_task[0], s_task[1], tid);
                __syncthreads();
                if (tid == 0) { __threadfence(); atomicAdd(&g_cnt[s_task[0]], 1); }
            }
        }
    };

    // L2-friendly raster: GROUP_M=8 supertiles
    constexpr int NT2 = NN / BN;   // 32
    constexpr int GROUP = 8;
    const int bid = blockIdx.x;
    const int tpg = GROUP * NT2;   // 256 (~one 2-CTA/SM wave)
    const int g = bid / tpg;
    const int r = bid % tpg;
    const int mt = g * GROUP + (r % GROUP);
    const int nt = r / GROUP;
    const int m0 = mt * BM;
    const int n0 = nt * BN;

    // per-thread cp.async mapping: idx = tid + t*256; row = idx>>3, chunk = idx&7
    uint64_t a_gbase[4], b_gbase[4];
    uint32_t a_soff[4], b_soff[4];
    #pragma unroll
    for (int t = 0; t < 4; t++) {
        int idx = tid + t * 256;
        int row = idx >> 3;
        int ch  = idx & 7;
        a_gbase[t] = __cvta_generic_to_global(
            g_xh + (size_t)(m0 + row) * KK + ch * 8);
        b_gbase[t] = __cvta_generic_to_global(
            g_wh + (size_t)(n0 + row) * KK + ch * 8);
        a_soff[t] = sw_off(row, ch);
        b_soff[t] = sw_off(row, ch) + A_STAGE_BYTES;
    }

    // prologue: ensure k-blocks 0..STAGES-2 converted, then fill stages
    #pragma unroll 1
    for (int s = 0; s < STAGES - 1; s++) {
        help_until(s);
        const uint32_t sbase = sb + s * STAGE_BYTES;
        const uint64_t koff = (uint64_t)s * BK * 2;
        #pragma unroll
        for (int t = 0; t < 4; t++) {
            CP_ASYNC16(sbase + a_soff[t], a_gbase[t] + koff);
            CP_ASYNC16(sbase + b_soff[t], b_gbase[t] + koff);
        }
        CP_COMMIT();
    }

    float acc[4][4][4];
    #pragma unroll
    for (int mi = 0; mi < 4; mi++)
        #pragma unroll
        for (int ni = 0; ni < 4; ni++)
            #pragma unroll
            for (int e = 0; e < 4; e++)
                acc[mi][ni][e] = 0.f;

    const int lrow = lane & 15;          // rows 0..15
    const int khalf = lane >> 4;         // 0: k0-7 chunk, 1: k8-15 chunk

    #pragma unroll 1
    for (int kt = 0; kt < KT; kt++) {
        CP_WAIT(STAGES - 2);

        const int ktl = kt + STAGES - 1;

        // tid0: publish last iter's chunk (stores long drained), check gate,
        // and grab one overlap chunk for this iteration.
        if (tid == 0) {
            if (pend_kb >= 0) {
                __threadfence();
                atomicAdd(&g_cnt[pend_kb], 1);
                pend_kb = -1;
            }
            advance_ready();
            if (ktl < KT && ktl > last_ready) {
                s_task[2] = 0;           // rare blocking path (startup)
            } else {
                __threadfence();         // order cnt observation vs cp.async
                int kbf, cf;
                grab_one(kbf, cf);
                s_task[0] = kbf; s_task[1] = cf; s_task[2] = 1;
            }
        }
        __syncthreads();

        int my_kb = -1, my_c = -1;
        if (s_task[2]) { my_kb = s_task[0]; my_c = s_task[1]; }
        else help_until(ktl);            // blocks + helps until ready

        // issue loads for k-tile ktl
        if (ktl < KT) {
            const int s = ktl % STAGES;
            const uint32_t sbase = sb + s * STAGE_BYTES;
            const uint64_t koff = (uint64_t)ktl * BK * 2;
            #pragma unroll
            for (int t = 0; t < 4; t++) {
                CP_ASYNC16(sbase + a_soff[t], a_gbase[t] + koff);
                CP_ASYNC16(sbase + b_soff[t], b_gbase[t] + koff);
            }
        }
        CP_COMMIT();

        // overlap conversion: stores complete under the MMAs below
        if (my_kb >= 0) {
            convert_chunk(xp, wp, my_kb, my_c, tid);
            if (tid == 0) pend_kb = my_kb;
        }

        // compute on stage kt % STAGES
        const uint32_t abase = sb + (kt % STAGES) * STAGE_BYTES;
        const uint32_t bbase = abase + A_STAGE_BYTES;

        #pragma unroll
        for (int ks = 0; ks < BK / 16; ks++) {
            const int ch = ks * 2 + khalf;

            uint32_t afr[4][4];
            #pragma unroll
            for (int mi = 0; mi < 4; mi++) {
                const int row = warp_m * 64 + mi * 16 + lrow;
                ldsm4(afr[mi], abase + sw_off(row, ch));
            }
            uint32_t bfr[4][2];
            #pragma unroll
            for (int nb = 0; nb < 2; nb++) {
                const int row = warp_n * 32 + nb * 16 + lrow;
                uint32_t t4[4];
                ldsm4(t4, bbase + sw_off(row, ch));
                bfr[nb * 2 + 0][0] = t4[0]; bfr[nb * 2 + 0][1] = t4[2];
                bfr[nb * 2 + 1][0] = t4[1]; bfr[nb * 2 + 1][1] = t4[3];
            }
            #pragma unroll
            for (int mi = 0; mi < 4; mi++)
                #pragma unroll
                for (int ni = 0; ni < 4; ni++)
                    mma16816(acc[mi][ni], afr[mi], bfr[ni]);
        }
        __syncthreads();
    }

    // publish any still-pending chunk before exiting (others may wait on it)
    if (tid == 0 && pend_kb >= 0) {
        __threadfence();
        atomicAdd(&g_cnt[pend_kb], 1);
    }

    // Epilogue: scale+bias, float2 stores (quad = 32B sector)
    const int colbase = n0 + warp_n * 32 + (lane & 3) * 2;
    const int rowbase = m0 + warp_m * 64 + (lane >> 2);

    float2 sc2[4], bi2[4];
    #pragma unroll
    for (int ni = 0; ni < 4; ni++) {
        const int c = colbase + ni * 8;
        sc2[ni] = *reinterpret_cast<const float2*>(scale + c);
        bi2[ni] = *reinterpret_cast<const float2*>(bias + c);
    }

    #pragma unroll
    for (int mi = 0; mi < 4; mi++) {
        const int r0 = rowbase + mi * 16;
        #pragma unroll
        for (int ni = 0; ni < 4; ni++) {
            const int c = colbase + ni * 8;
            float2 v0, v1;
            v0.x = acc[mi][ni][0] * sc2[ni].x + bi2[ni].x;
            v0.y = acc[mi][ni][1] * sc2[ni].y + bi2[ni].y;
            v1.x = acc[mi][ni][2] * sc2[ni].x + bi2[ni].x;
            v1.y = acc[mi][ni][3] * sc2[ni].y + bi2[ni].y;
            *reinterpret_cast<float2*>(out + (size_t)r0 * NN + c) = v0;
            *reinterpret_cast<float2*>(out + (size_t)(r0 + 8) * NN + c) = v1;
        }
    }
}

// ---------------- host launch ----------------
extern "C" void kernel_launch(void* const* d_in, const int* in_sizes, int n_in,
                              void* d_out, int out_size) {
    const float* x  = (const float*)d_in[0];  // (B,S,IN)  8192 x 4096
    const float* w  = (const float*)d_in[1];  // (OUT,IN)  4096 x 4096
    const float* sc = (const float*)d_in[2];  // (OUT,)
    const float* bi = (const float*)d_in[3];  // (OUT,)
    float* out = (float*)d_out;

    cudaFuncSetAttribute(gemm_kernel, cudaFuncAttributeMaxDynamicSharedMemorySize,
                         SMEM_TOTAL);

    // 1) reset conversion progress (determinism across graph replays)
    init_kernel<<<1, 64>>>();

    // 2) fused convert + HMMA GEMM + scale/bias epilogue
    const int grid = (MM / BM) * (NN / BN);  // 2048 CTAs
    gemm_kernel<<<grid, 256, SMEM_TOTAL>>>(out, sc, bi, x, w);
}